// round 5
// baseline (speedup 1.0000x reference)
#include <cuda_runtime.h>
#include <cstdint>

#define BB   32
#define TT   336
#define NH   100
#define NM   150
#define FH   8
#define FM   16
#define HG   64
#define HL   64
#define FUT  24
#define TC   16   // timesteps per xgemm block

typedef unsigned long long u64;

// Packed fp32 FMA (per-lane .rn, bitwise == scalar FFMA)
#define FMA2(d, a, b) \
    asm("fma.rn.f32x2 %0, %1, %2, %0;" : "+l"(d) : "l"(a), "l"(b))
#define UNPACK2(lo, hi, x) \
    asm("mov.b64 {%0, %1}, %2;" : "=f"(lo), "=f"(hi) : "l"(x))

// GNN output x: [n][t][b][hg]
__device__ float g_x[(size_t)NH * TT * BB * HG];
// Precomputed x-gates(+bias), per-consumer-thread tiles:
// [n][t][tid][16 u64]  (tid tile: 4 batches x 4 gates x 2 units)
__device__ u64 g_gates2[(size_t)NH * TT * 4096];

// ---------------------------------------------------------------------------
// Kernel A: hetero GraphConv, one graph (b,t) per block. (unchanged)
// ---------------------------------------------------------------------------
__global__ void __launch_bounds__(256) gnn_kernel(
    const float* __restrict__ xm_all, const float* __restrict__ xh_all,
    const int* __restrict__ eh, const int* __restrict__ em,
    const float* __restrict__ Wrel_m, const float* __restrict__ brel_m,
    const float* __restrict__ Wroot_m,
    const float* __restrict__ Wrel_h, const float* __restrict__ brel_h,
    const float* __restrict__ Wroot_h,
    int Eh, int Em)
{
    __shared__ float sxh[NH * FH];
    __shared__ float sxm[NM * FM];
    __shared__ float sah[NH * FH];
    __shared__ float sam[NH * FM];
    __shared__ float swh[HG * FH];
    __shared__ float swm[HG * FM];
    __shared__ float swr[HG * FH];
    __shared__ float sb[HG];

    const int g = blockIdx.x;
    const int t = g % TT;
    const int b = g / TT;
    const int tid = threadIdx.x;

    const float* xh = xh_all + (size_t)g * NH * FH;
    const float* xm = xm_all + (size_t)g * NM * FM;

    for (int i = tid; i < NH * FH; i += 256) { sxh[i] = xh[i]; sah[i] = 0.f; }
    for (int i = tid; i < NM * FM; i += 256) sxm[i] = xm[i];
    for (int i = tid; i < NH * FM; i += 256) sam[i] = 0.f;
    for (int i = tid; i < HG * FH; i += 256) {
        swh[i] = 0.5f * Wrel_h[i];
        swr[i] = 0.5f * (Wroot_h[i] + Wroot_m[i]);
    }
    for (int i = tid; i < HG * FM; i += 256) swm[i] = 0.5f * Wrel_m[i];
    for (int i = tid; i < HG;      i += 256) sb[i]  = 0.5f * (brel_h[i] + brel_m[i]);
    __syncthreads();

    for (int e = tid; e < Eh; e += 256) {
        int s  = eh[e];
        int tg = eh[Eh + e];
        #pragma unroll
        for (int f = 0; f < FH; f++)
            atomicAdd(&sah[tg * FH + f], sxh[s * FH + f]);
    }
    for (int e = tid; e < Em; e += 256) {
        int s  = em[e];
        int tg = em[Em + e];
        #pragma unroll
        for (int f = 0; f < FM; f++)
            atomicAdd(&sam[tg * FM + f], sxm[s * FM + f]);
    }
    __syncthreads();

    for (int idx = tid; idx < NH * HG; idx += 256) {
        int n = idx / HG;
        int j = idx % HG;
        float acc = sb[j];
        #pragma unroll
        for (int k = 0; k < FH; k++)
            acc += sah[n * FH + k] * swh[j * FH + k]
                 + sxh[n * FH + k] * swr[j * FH + k];
        #pragma unroll
        for (int k = 0; k < FM; k++)
            acc += sam[n * FM + k] * swm[j * FM + k];
        float v = acc > 0.f ? acc : 0.01f * acc;
        g_x[(((size_t)n * TT + t) * BB + b) * HG + j] = v;
    }
}

// ---------------------------------------------------------------------------
// Shared weight repack:  W[j=0..255][k=0..63]  ->
//   sW2[k*256 + (gg>>1)*128 + tn*4 + (gg&1)*2 + du]   (j = gg*64 + 2*tn + du)
// Thread (tn) then reads its 8 weights for k as two conflict-free LDS.128.
// ---------------------------------------------------------------------------

// ---------------------------------------------------------------------------
// Kernel B: x-gate precompute. grid (NH, TT/TC), 256 thr, 2 blocks/SM.
// ---------------------------------------------------------------------------
#define XG_SW 0                     // 16384
#define XG_SB 16384                 // 256
#define XG_XD (16384 + 256)         // xdup [k][2b] stride 66: 4224
#define XG_FLOATS (XG_XD + 64*66)
#define XG_BYTES  (XG_FLOATS * 4)

__global__ void __launch_bounds__(256, 2) xgemm_kernel(
    const float* __restrict__ W_ih,
    const float* __restrict__ b_ih, const float* __restrict__ b_hh)
{
    extern __shared__ float sm[];
    float* sW2   = sm + XG_SW;
    float* sbias = sm + XG_SB;
    float* xd    = sm + XG_XD;

    const int n   = blockIdx.x;
    const int t0  = blockIdx.y * TC;
    const int tid = threadIdx.x;

    const float* w = W_ih + (size_t)n * 16384;
    for (int i = tid; i < 16384; i += 256) {
        int j = i >> 6, k = i & 63;
        int gg = j >> 6, u = j & 63, tn2 = u >> 1, du = u & 1;
        sW2[k * 256 + (gg >> 1) * 128 + tn2 * 4 + (gg & 1) * 2 + du] = w[i];
    }
    sbias[tid] = b_ih[n * 256 + tid] + b_hh[n * 256 + tid];
    __syncthreads();

    const int tm = tid >> 5;          // batch group 0..7
    const int tn = tid & 31;          // unit pair
    const int st_b2 = (tid >> 3) * 2; // staging: 2*batch
    const int st_k  = (tid & 7) * 8;  // staging: k base

    u64 bias4[4];
    #pragma unroll
    for (int gg = 0; gg < 4; gg++)
        bias4[gg] = *(const u64*)&sbias[gg * 64 + 2 * tn];

    const float* xbase = g_x + ((size_t)n * TT + t0) * BB * HG;
    u64* gbase = g_gates2 + ((size_t)(n * TT + t0)) * 4096 + tid * 16;

    for (int tt = 0; tt < TC; tt++) {
        // stage x_t duplicated: xd[k][2b] = {v, v}
        const float* xt = xbase + (size_t)tt * BB * HG;
        float4 v0 = *(const float4*)&xt[(tid >> 3) * HG + st_k];
        float4 v1 = *(const float4*)&xt[(tid >> 3) * HG + st_k + 4];
        *(float2*)&xd[(st_k + 0) * 66 + st_b2] = make_float2(v0.x, v0.x);
        *(float2*)&xd[(st_k + 1) * 66 + st_b2] = make_float2(v0.y, v0.y);
        *(float2*)&xd[(st_k + 2) * 66 + st_b2] = make_float2(v0.z, v0.z);
        *(float2*)&xd[(st_k + 3) * 66 + st_b2] = make_float2(v0.w, v0.w);
        *(float2*)&xd[(st_k + 4) * 66 + st_b2] = make_float2(v1.x, v1.x);
        *(float2*)&xd[(st_k + 5) * 66 + st_b2] = make_float2(v1.y, v1.y);
        *(float2*)&xd[(st_k + 6) * 66 + st_b2] = make_float2(v1.z, v1.z);
        *(float2*)&xd[(st_k + 7) * 66 + st_b2] = make_float2(v1.w, v1.w);
        __syncthreads();

        u64 acc[16];
        #pragma unroll
        for (int mi = 0; mi < 4; mi++)
            #pragma unroll
            for (int gg = 0; gg < 4; gg++) acc[mi * 4 + gg] = bias4[gg];

        #pragma unroll 8
        for (int k = 0; k < 64; k++) {
            float4 wA = *(const float4*)&sW2[k * 256 + tn * 4];
            float4 wB = *(const float4*)&sW2[k * 256 + 128 + tn * 4];
            u64 w0 = *(const u64*)&wA.x;
            u64 w1 = *(const u64*)&wA.z;
            u64 w2 = *(const u64*)&wB.x;
            u64 w3 = *(const u64*)&wB.z;
            #pragma unroll
            for (int mi = 0; mi < 4; mi++) {
                u64 xx = *(const u64*)&xd[k * 66 + 8 * tm + 2 * mi];
                FMA2(acc[mi * 4 + 0], xx, w0);
                FMA2(acc[mi * 4 + 1], xx, w1);
                FMA2(acc[mi * 4 + 2], xx, w2);
                FMA2(acc[mi * 4 + 3], xx, w3);
            }
        }

        u64* gt = gbase + (size_t)tt * 4096;
        #pragma unroll
        for (int q = 0; q < 16; q++) gt[q] = acc[q];
        __syncthreads();
    }
}

// ---------------------------------------------------------------------------
// Kernel C: recurrent LSTM. One block per node, 256 threads, 1 sync/step.
// Double-buffered duplicated h, double-banked register accumulators that are
// directly LDG-prefetched with the next step's x-gates.
// ---------------------------------------------------------------------------
#define L_SW2  0                        // 16384
#define L_HD   16384                    // 2 x [k][2b] stride 66: 2*4224
#define L_WL   (L_HD + 2*4224)          // 24*64
#define L_BL   (L_WL + 24*64)
#define LS_FLOATS (L_BL + 32)
#define LS_BYTES  (LS_FLOATS * 4)

__device__ __forceinline__ float sigm(float x) {
    return 1.0f / (1.0f + __expf(-x));
}
__device__ __forceinline__ float tanh_fast(float x) {
    float xc = fminf(fmaxf(x, -15.f), 15.f);
    float e = __expf(2.0f * xc);
    return (e - 1.0f) / (e + 1.0f);
}

__global__ void __launch_bounds__(256) lstm_kernel(
    const float* __restrict__ W_hh,
    const float* __restrict__ W_lin, const float* __restrict__ b_lin,
    float* __restrict__ out)
{
    extern __shared__ float sm[];
    float* sW2   = sm + L_SW2;
    float* hd    = sm + L_HD;
    float* sWlin = sm + L_WL;
    float* sblin = sm + L_BL;

    const int n   = blockIdx.x;
    const int tid = threadIdx.x;
    const int tm  = tid >> 5;
    const int tn  = tid & 31;

    const float* whh = W_hh + (size_t)n * 16384;
    for (int i = tid; i < 16384; i += 256) {
        int j = i >> 6, k = i & 63;
        int gg = j >> 6, u = j & 63, tn2 = u >> 1, du = u & 1;
        sW2[k * 256 + (gg >> 1) * 128 + tn2 * 4 + (gg & 1) * 2 + du] = whh[i];
    }
    for (int i = tid; i < FUT * HL; i += 256) sWlin[i] = W_lin[i];
    if (tid < FUT) sblin[tid] = b_lin[tid];
    for (int i = tid; i < 2 * 4224; i += 256) hd[i] = 0.f;

    float c[4][2];
    #pragma unroll
    for (int mi = 0; mi < 4; mi++) { c[mi][0] = 0.f; c[mi][1] = 0.f; }

    const u64* gp = g_gates2 + (size_t)n * TT * 4096 + tid * 16;

    u64 accA[16], accB[16];
    #pragma unroll
    for (int q = 0; q < 16; q++) { accA[q] = gp[q]; accB[q] = gp[4096 + q]; }

    // one step: consume acc (holds gates(t) and accumulates W_hh@h(t)),
    // write h(t+1) into hw (dup), then prefetch gates(t+2) into acc.
    auto step = [&](u64 (&acc)[16], const float* hb, float* hw, int tp2) {
        __syncthreads();   // h(t) writes visible
        #pragma unroll 8
        for (int k = 0; k < 64; k++) {
            float4 wA = *(const float4*)&sW2[k * 256 + tn * 4];
            float4 wB = *(const float4*)&sW2[k * 256 + 128 + tn * 4];
            u64 w0 = *(const u64*)&wA.x;
            u64 w1 = *(const u64*)&wA.z;
            u64 w2 = *(const u64*)&wB.x;
            u64 w3 = *(const u64*)&wB.z;
            #pragma unroll
            for (int mi = 0; mi < 4; mi++) {
                u64 hx = *(const u64*)&hd[(hb - hd) + k * 66 + 8 * tm + 2 * mi];
                FMA2(acc[mi * 4 + 0], hx, w0);
                FMA2(acc[mi * 4 + 1], hx, w1);
                FMA2(acc[mi * 4 + 2], hx, w2);
                FMA2(acc[mi * 4 + 3], hx, w3);
            }
        }
        // cell update (gate order i, f, g, o)
        #pragma unroll
        for (int mi = 0; mi < 4; mi++) {
            float iv[2], fv[2], gv[2], ov[2];
            UNPACK2(iv[0], iv[1], acc[mi * 4 + 0]);
            UNPACK2(fv[0], fv[1], acc[mi * 4 + 1]);
            UNPACK2(gv[0], gv[1], acc[mi * 4 + 2]);
            UNPACK2(ov[0], ov[1], acc[mi * 4 + 3]);
            #pragma unroll
            for (int du = 0; du < 2; du++) {
                float ig = sigm(iv[du]);
                float fg = sigm(fv[du]);
                float gg = tanh_fast(gv[du]);
                float og = sigm(ov[du]);
                float cc = fg * c[mi][du] + ig * gg;
                c[mi][du] = cc;
                float hv = og * tanh_fast(cc);
                *(float2*)&hw[(2 * tn + du) * 66 + 8 * tm + 2 * mi] =
                    make_float2(hv, hv);
            }
        }
        // prefetch gates(t+2) directly into the (now free) accumulator bank
        if (tp2 < TT) {
            const u64* gn = gp + (size_t)tp2 * 4096;
            #pragma unroll
            for (int q = 0; q < 16; q++) acc[q] = gn[q];
        }
    };

    float* buf0 = hd;
    float* buf1 = hd + 4224;
    for (int t = 0; t < TT; t += 2) {
        step(accA, buf0, buf1, t + 2);       // even step: h(t) in buf0
        step(accB, buf1, buf0, t + 3);       // odd step:  h(t+1) in buf1
    }
    __syncthreads();

    // h_last in buf0 (TT even); hd[u*66 + 2b]
    for (int idx = tid; idx < BB * FUT; idx += 256) {
        int b = idx / FUT;
        int f = idx % FUT;
        float acc = sblin[f];
        #pragma unroll
        for (int u = 0; u < HL; u++)
            acc += buf0[u * 66 + 2 * b] * sWlin[f * HL + u];
        float v = acc > 0.f ? acc : 0.01f * acc;
        out[((size_t)b * NH + n) * FUT + f] = v;
    }
}

// ---------------------------------------------------------------------------
extern "C" void kernel_launch(void* const* d_in, const int* in_sizes, int n_in,
                              void* d_out, int out_size)
{
    const float* data_meteo = (const float*)d_in[0];
    const float* data_hydro = (const float*)d_in[1];
    const int*   eh         = (const int*)  d_in[2];
    const int*   em         = (const int*)  d_in[3];
    const float* W_rel_m    = (const float*)d_in[4];
    const float* b_rel_m    = (const float*)d_in[5];
    const float* W_root_m   = (const float*)d_in[6];
    const float* W_rel_h    = (const float*)d_in[7];
    const float* b_rel_h    = (const float*)d_in[8];
    const float* W_root_h   = (const float*)d_in[9];
    const float* W_ih       = (const float*)d_in[10];
    const float* W_hh       = (const float*)d_in[11];
    const float* b_ih       = (const float*)d_in[12];
    const float* b_hh       = (const float*)d_in[13];
    const float* W_lin      = (const float*)d_in[14];
    const float* b_lin      = (const float*)d_in[15];

    const int Eh = in_sizes[2] / 2;
    const int Em = in_sizes[3] / 2;

    gnn_kernel<<<BB * TT, 256>>>(data_meteo, data_hydro, eh, em,
                                 W_rel_m, b_rel_m, W_root_m,
                                 W_rel_h, b_rel_h, W_root_h,
                                 Eh, Em);

    cudaFuncSetAttribute(xgemm_kernel,
                         cudaFuncAttributeMaxDynamicSharedMemorySize, XG_BYTES);
    dim3 xg(NH, TT / TC);
    xgemm_kernel<<<xg, 256, XG_BYTES>>>(W_ih, b_ih, b_hh);

    cudaFuncSetAttribute(lstm_kernel,
                         cudaFuncAttributeMaxDynamicSharedMemorySize, LS_BYTES);
    lstm_kernel<<<NH, 256, LS_BYTES>>>(W_hh, W_lin, b_lin, (float*)d_out);
}

// round 6
// speedup vs baseline: 1.6312x; 1.6312x over previous
#include <cuda_runtime.h>
#include <cstdint>

#define BB   32
#define TT   336
#define NH   100
#define NM   150
#define FH   8
#define FM   16
#define HG   64
#define HL   64
#define FUT  24
#define TC   16   // timesteps per precompute block
#define TB   16   // graphs per gnn block

// GNN output x: [n][t][b][hg]
__device__ float g_x[(size_t)NH * TT * BB * HG];
// Precomputed x-gates (+bias): [n][t][b][256]
__device__ float g_gates[(size_t)NH * TT * BB * 256];

// CSR edge structure (built once per launch, deterministic order)
__device__ int d_off_h[NH], d_deg_h[NH], d_src_h[512];
__device__ int d_off_m[NH], d_deg_m[NH], d_src_m[1024];

// ---------------------------------------------------------------------------
// Kernel A0: build CSR by target node. One block; thread n collects sources
// for target n in original edge order (deterministic).
// ---------------------------------------------------------------------------
__global__ void __launch_bounds__(256) csr_kernel(
    const int* __restrict__ eh, const int* __restrict__ em, int Eh, int Em)
{
    __shared__ int s_src[1024], s_tgt[1024];
    const int tid = threadIdx.x;

    for (int i = tid; i < Eh; i += 256) { s_src[i] = eh[i]; s_tgt[i] = eh[Eh + i]; }
    __syncthreads();
    if (tid < NH) {
        int start = 0;
        for (int e = 0; e < Eh; e++) start += (s_tgt[e] < tid) ? 1 : 0;
        int p = start, cnt = 0;
        for (int e = 0; e < Eh; e++)
            if (s_tgt[e] == tid) { d_src_h[p++] = s_src[e]; cnt++; }
        d_off_h[tid] = start; d_deg_h[tid] = cnt;
    }
    __syncthreads();
    for (int i = tid; i < Em; i += 256) { s_src[i] = em[i]; s_tgt[i] = em[Em + i]; }
    __syncthreads();
    if (tid < NH) {
        int start = 0;
        for (int e = 0; e < Em; e++) start += (s_tgt[e] < tid) ? 1 : 0;
        int p = start, cnt = 0;
        for (int e = 0; e < Em; e++)
            if (s_tgt[e] == tid) { d_src_m[p++] = s_src[e]; cnt++; }
        d_off_m[tid] = start; d_deg_m[tid] = cnt;
    }
}

// ---------------------------------------------------------------------------
// Kernel A: hetero GraphConv, TB graphs per block, CSR gather (no atomics),
// transposed weights in SMEM (conflict-free broadcast reads).
// ---------------------------------------------------------------------------
__global__ void __launch_bounds__(256) gnn_kernel(
    const float* __restrict__ xm_all, const float* __restrict__ xh_all,
    const float* __restrict__ Wrel_m, const float* __restrict__ brel_m,
    const float* __restrict__ Wroot_m,
    const float* __restrict__ Wrel_h, const float* __restrict__ brel_h,
    const float* __restrict__ Wroot_h)
{
    __shared__ float swh[FH * HG];    // 0.5*W_rel_h transposed [k][j]
    __shared__ float swr[FH * HG];    // 0.5*(W_root_h+W_root_m) transposed
    __shared__ float swm[FM * HG];    // 0.5*W_rel_m transposed
    __shared__ float sb[HG];
    __shared__ int soff_h[NH], sdeg_h[NH], ssrc_h[512];
    __shared__ int soff_m[NH], sdeg_m[NH], ssrc_m[1024];
    __shared__ float sxh[NH * FH];    // 800
    __shared__ float sxm[NM * FM];    // 2400
    __shared__ float sah[NH * FH];    // 800
    __shared__ float sam[NH * FM];    // 1600

    const int tid = threadIdx.x;

    for (int i = tid; i < HG * FH; i += 256) {
        int j = i / FH, k = i % FH;
        swh[k * HG + j] = 0.5f * Wrel_h[i];
        swr[k * HG + j] = 0.5f * (Wroot_h[i] + Wroot_m[i]);
    }
    for (int i = tid; i < HG * FM; i += 256) {
        int j = i / FM, k = i % FM;
        swm[k * HG + j] = 0.5f * Wrel_m[i];
    }
    for (int i = tid; i < HG; i += 256) sb[i] = 0.5f * (brel_h[i] + brel_m[i]);
    for (int i = tid; i < NH; i += 256) {
        soff_h[i] = d_off_h[i]; sdeg_h[i] = d_deg_h[i];
        soff_m[i] = d_off_m[i]; sdeg_m[i] = d_deg_m[i];
    }
    for (int i = tid; i < 512;  i += 256) ssrc_h[i] = d_src_h[i];
    for (int i = tid; i < 1024; i += 256) ssrc_m[i] = d_src_m[i];

    for (int gi = 0; gi < TB; gi++) {
        const int g = blockIdx.x * TB + gi;
        const float* xh = xh_all + (size_t)g * NH * FH;
        const float* xm = xm_all + (size_t)g * NM * FM;

        __syncthreads();   // previous graph's reads done (and first-iter setup)
        for (int i = tid; i < NH * FH / 4; i += 256)
            *(float4*)&sxh[i * 4] = *(const float4*)&xh[i * 4];
        for (int i = tid; i < NM * FM / 4; i += 256)
            *(float4*)&sxm[i * 4] = *(const float4*)&xm[i * 4];
        __syncthreads();

        // CSR-gather aggregation (deterministic order)
        for (int idx = tid; idx < NH * FH; idx += 256) {
            int n = idx >> 3, k = idx & 7;
            int o = soff_h[n], d = sdeg_h[n];
            float s = 0.f;
            for (int e = 0; e < d; e++) s += sxh[ssrc_h[o + e] * FH + k];
            sah[idx] = s;
        }
        for (int idx = tid; idx < NH * FM; idx += 256) {
            int n = idx >> 4, k = idx & 15;
            int o = soff_m[n], d = sdeg_m[n];
            float s = 0.f;
            for (int e = 0; e < d; e++) s += sxm[ssrc_m[o + e] * FM + k];
            sam[idx] = s;
        }
        __syncthreads();

        // out[n][j] with transposed weights (broadcast agg, coalesced weights)
        const int t = g % TT;
        const int b = g / TT;
        for (int idx = tid; idx < NH * HG; idx += 256) {
            int n = idx >> 6, j = idx & 63;
            float acc = sb[j];
            #pragma unroll
            for (int k = 0; k < FH; k++)
                acc += sah[n * FH + k] * swh[k * HG + j]
                     + sxh[n * FH + k] * swr[k * HG + j];
            #pragma unroll
            for (int k = 0; k < FM; k++)
                acc += sam[n * FM + k] * swm[k * HG + j];
            float v = acc > 0.f ? acc : 0.01f * acc;
            g_x[(((size_t)n * TT + t) * BB + b) * HG + j] = v;
        }
    }
}

// ---------------------------------------------------------------------------
// Kernel B: x-gate precompute. grid (NH, TT/TC), 256 threads, 3 blocks/SM.
// (exact Round-2 version, verified)
// ---------------------------------------------------------------------------
#define XG_SW 0                 // [k][j] stride 256  (16384 floats)
#define XG_SB 16384             // 256
#define XG_SX (16384 + 256)     // [k][b] stride 33
#define XG_FLOATS (XG_SX + 64*33)
#define XG_BYTES  (XG_FLOATS * 4)

__global__ void __launch_bounds__(256, 3) xgemm_kernel(
    const float* __restrict__ W_ih,
    const float* __restrict__ b_ih, const float* __restrict__ b_hh)
{
    extern __shared__ float sm[];
    float* sW = sm + XG_SW;
    float* sb = sm + XG_SB;
    float* sx = sm + XG_SX;

    const int n   = blockIdx.x;
    const int t0  = blockIdx.y * TC;
    const int tid = threadIdx.x;

    const float* w = W_ih + (size_t)n * 256 * 64;
    for (int i = tid; i < 16384; i += 256) {
        int j = i >> 6, k = i & 63;
        sW[k * 256 + j] = w[i];
    }
    sb[tid] = b_ih[n * 256 + tid] + b_hh[n * 256 + tid];

    const int tm = tid >> 5;
    const int tn = tid & 31;
    const int sb_b = tid >> 3;
    const int sb_k = (tid & 7) << 3;

    const float* xbase = g_x + ((size_t)n * TT + t0) * BB * HG;
    float* gbase = g_gates + ((size_t)n * TT + t0) * BB * 256;
    __syncthreads();

    for (int tt = 0; tt < TC; tt++) {
        const float* xt = xbase + (size_t)tt * BB * HG;
        float4 v0 = *(const float4*)&xt[sb_b * HG + sb_k];
        float4 v1 = *(const float4*)&xt[sb_b * HG + sb_k + 4];
        sx[(sb_k + 0) * 33 + sb_b] = v0.x;
        sx[(sb_k + 1) * 33 + sb_b] = v0.y;
        sx[(sb_k + 2) * 33 + sb_b] = v0.z;
        sx[(sb_k + 3) * 33 + sb_b] = v0.w;
        sx[(sb_k + 4) * 33 + sb_b] = v1.x;
        sx[(sb_k + 5) * 33 + sb_b] = v1.y;
        sx[(sb_k + 6) * 33 + sb_b] = v1.z;
        sx[(sb_k + 7) * 33 + sb_b] = v1.w;
        __syncthreads();

        float acc[4][8];
        #pragma unroll
        for (int mi = 0; mi < 4; mi++)
            #pragma unroll
            for (int gg = 0; gg < 4; gg++) {
                acc[mi][gg * 2 + 0] = sb[gg * 64 + 2 * tn + 0];
                acc[mi][gg * 2 + 1] = sb[gg * 64 + 2 * tn + 1];
            }

        #pragma unroll 4
        for (int k = 0; k < 64; k++) {
            float xv[4];
            #pragma unroll
            for (int mi = 0; mi < 4; mi++) xv[mi] = sx[k * 33 + 4 * tm + mi];
            #pragma unroll
            for (int gg = 0; gg < 4; gg++) {
                float2 wv = *(const float2*)&sW[k * 256 + gg * 64 + 2 * tn];
                #pragma unroll
                for (int mi = 0; mi < 4; mi++) {
                    acc[mi][gg * 2 + 0] += xv[mi] * wv.x;
                    acc[mi][gg * 2 + 1] += xv[mi] * wv.y;
                }
            }
        }

        float* gt = gbase + (size_t)tt * BB * 256;
        #pragma unroll
        for (int mi = 0; mi < 4; mi++)
            #pragma unroll
            for (int gg = 0; gg < 4; gg++) {
                float2 v; v.x = acc[mi][gg * 2]; v.y = acc[mi][gg * 2 + 1];
                *(float2*)&gt[(4 * tm + mi) * 256 + gg * 64 + 2 * tn] = v;
            }
        __syncthreads();
    }
}

// ---------------------------------------------------------------------------
// Kernel C: recurrent LSTM (h-half), double-buffered h, gmem gate prefetch.
// (exact Round-2 version, verified)
// ---------------------------------------------------------------------------
#define O_WHH 0
#define O_H   16384
#define HBUF  (64*33)
#define O_WL  (O_H + 2*HBUF)
#define O_BL  (O_WL + 24*64)
#define LS_FLOATS (O_BL + 32)
#define LS_BYTES  (LS_FLOATS * 4)

__device__ __forceinline__ float sigm(float x) {
    return 1.0f / (1.0f + __expf(-x));
}
__device__ __forceinline__ float tanh_fast(float x) {
    float xc = fminf(fmaxf(x, -15.f), 15.f);
    float e = __expf(2.0f * xc);
    return (e - 1.0f) / (e + 1.0f);
}

__global__ void __launch_bounds__(256) lstm_kernel(
    const float* __restrict__ W_hh,
    const float* __restrict__ W_lin, const float* __restrict__ b_lin,
    float* __restrict__ out)
{
    extern __shared__ float sm[];
    float* sWhh  = sm + O_WHH;
    float* sh    = sm + O_H;
    float* sWlin = sm + O_WL;
    float* sblin = sm + O_BL;

    const int n   = blockIdx.x;
    const int tid = threadIdx.x;

    const float* whh = W_hh + (size_t)n * 256 * 64;
    for (int i = tid; i < 16384; i += 256) {
        int j = i >> 6, k = i & 63;
        sWhh[k * 256 + j] = whh[i];
    }
    for (int i = tid; i < FUT * HL; i += 256) sWlin[i] = W_lin[i];
    if (tid < FUT) sblin[tid] = b_lin[tid];
    for (int i = tid; i < HBUF; i += 256) sh[i] = 0.f;

    const int tm = tid >> 5;
    const int tn = tid & 31;

    float c[4][2];
    #pragma unroll
    for (int mi = 0; mi < 4; mi++) { c[mi][0] = 0.f; c[mi][1] = 0.f; }

    const float* gptr = g_gates + (size_t)n * TT * BB * 256;

    float gb[4][8];
    #pragma unroll
    for (int mi = 0; mi < 4; mi++)
        #pragma unroll
        for (int gg = 0; gg < 4; gg++) {
            float2 v = *(const float2*)&gptr[(4 * tm + mi) * 256 + gg * 64 + 2 * tn];
            gb[mi][gg * 2] = v.x; gb[mi][gg * 2 + 1] = v.y;
        }

    for (int t = 0; t < TT; t++) {
        float acc[4][8];
        #pragma unroll
        for (int mi = 0; mi < 4; mi++)
            #pragma unroll
            for (int q = 0; q < 8; q++) acc[mi][q] = gb[mi][q];

        if (t + 1 < TT) {
            const float* gnx = gptr + (size_t)(t + 1) * BB * 256;
            #pragma unroll
            for (int mi = 0; mi < 4; mi++)
                #pragma unroll
                for (int gg = 0; gg < 4; gg++) {
                    float2 v = *(const float2*)&gnx[(4 * tm + mi) * 256 + gg * 64 + 2 * tn];
                    gb[mi][gg * 2] = v.x; gb[mi][gg * 2 + 1] = v.y;
                }
        }

        const float* hb = sh + (t & 1) * HBUF;
        float*       hw = sh + ((t + 1) & 1) * HBUF;
        __syncthreads();

        #pragma unroll 4
        for (int k = 0; k < 64; k++) {
            float hv[4];
            #pragma unroll
            for (int mi = 0; mi < 4; mi++) hv[mi] = hb[k * 33 + 4 * tm + mi];
            #pragma unroll
            for (int gg = 0; gg < 4; gg++) {
                float2 w = *(const float2*)&sWhh[k * 256 + gg * 64 + 2 * tn];
                #pragma unroll
                for (int mi = 0; mi < 4; mi++) {
                    acc[mi][gg * 2 + 0] += hv[mi] * w.x;
                    acc[mi][gg * 2 + 1] += hv[mi] * w.y;
                }
            }
        }

        #pragma unroll
        for (int mi = 0; mi < 4; mi++) {
            #pragma unroll
            for (int du = 0; du < 2; du++) {
                float ig = sigm(acc[mi][0 * 2 + du]);
                float fg = sigm(acc[mi][1 * 2 + du]);
                float gg = tanh_fast(acc[mi][2 * 2 + du]);
                float og = sigm(acc[mi][3 * 2 + du]);
                float cc = fg * c[mi][du] + ig * gg;
                c[mi][du] = cc;
                hw[(2 * tn + du) * 33 + (4 * tm + mi)] = og * tanh_fast(cc);
            }
        }
    }
    __syncthreads();

    float* hl = sh + ((TT) & 1) * HBUF;
    for (int idx = tid; idx < BB * FUT; idx += 256) {
        int b = idx / FUT;
        int f = idx % FUT;
        float acc = sblin[f];
        #pragma unroll
        for (int u = 0; u < HL; u++)
            acc += hl[u * 33 + b] * sWlin[f * HL + u];
        float v = acc > 0.f ? acc : 0.01f * acc;
        out[((size_t)b * NH + n) * FUT + f] = v;
    }
}

// ---------------------------------------------------------------------------
extern "C" void kernel_launch(void* const* d_in, const int* in_sizes, int n_in,
                              void* d_out, int out_size)
{
    const float* data_meteo = (const float*)d_in[0];
    const float* data_hydro = (const float*)d_in[1];
    const int*   eh         = (const int*)  d_in[2];
    const int*   em         = (const int*)  d_in[3];
    const float* W_rel_m    = (const float*)d_in[4];
    const float* b_rel_m    = (const float*)d_in[5];
    const float* W_root_m   = (const float*)d_in[6];
    const float* W_rel_h    = (const float*)d_in[7];
    const float* b_rel_h    = (const float*)d_in[8];
    const float* W_root_h   = (const float*)d_in[9];
    const float* W_ih       = (const float*)d_in[10];
    const float* W_hh       = (const float*)d_in[11];
    const float* b_ih       = (const float*)d_in[12];
    const float* b_hh       = (const float*)d_in[13];
    const float* W_lin      = (const float*)d_in[14];
    const float* b_lin      = (const float*)d_in[15];

    const int Eh = in_sizes[2] / 2;
    const int Em = in_sizes[3] / 2;

    csr_kernel<<<1, 256>>>(eh, em, Eh, Em);

    gnn_kernel<<<(BB * TT) / TB, 256>>>(data_meteo, data_hydro,
                                        W_rel_m, b_rel_m, W_root_m,
                                        W_rel_h, b_rel_h, W_root_h);

    cudaFuncSetAttribute(xgemm_kernel,
                         cudaFuncAttributeMaxDynamicSharedMemorySize, XG_BYTES);
    dim3 xg(NH, TT / TC);
    xgemm_kernel<<<xg, 256, XG_BYTES>>>(W_ih, b_ih, b_hh);

    cudaFuncSetAttribute(lstm_kernel,
                         cudaFuncAttributeMaxDynamicSharedMemorySize, LS_BYTES);
    lstm_kernel<<<NH, 256, LS_BYTES>>>(W_hh, W_lin, b_lin, (float*)d_out);
}